// round 8
// baseline (speedup 1.0000x reference)
#include <cuda_runtime.h>
#include <cuda_bf16.h>

// Scratch
__device__ int   g_off[8193];
__device__ float g_sum[8192 * 256];   // per-segment column sums (up to B=8192)

// ---------------------------------------------------------------------------
// Kernel 1: single-block exclusive scan of node_num[B] -> g_off[0..B]
// ---------------------------------------------------------------------------
__global__ void scan_kernel(const int* __restrict__ node_num, int B) {
    const int tid = threadIdx.x;
    const int NT = 1024;
    const int items = (B + NT - 1) / NT;

    int v[8];
    int base = tid * items;
    int tsum = 0;
    #pragma unroll
    for (int i = 0; i < 8; ++i) {
        int idx = base + i;
        int val = (i < items && idx < B) ? node_num[idx] : 0;
        v[i] = tsum;
        tsum += val;
    }

    __shared__ int s[1024];
    s[tid] = tsum;
    __syncthreads();

    #pragma unroll
    for (int off = 1; off < 1024; off <<= 1) {
        int add = (tid >= off) ? s[tid - off] : 0;
        __syncthreads();
        s[tid] += add;
        __syncthreads();
    }

    int excl = s[tid] - tsum;

    #pragma unroll
    for (int i = 0; i < 8; ++i) {
        int idx = base + i;
        if (i < items && idx < B) g_off[idx] = excl + v[i];
    }
    if (tid == NT - 1) g_off[B] = s[NT - 1];
}

// ---------------------------------------------------------------------------
// Kernel 2 (phase 1): pure streaming per-segment column sums.
// 64 threads per CTA, one CTA per segment. Thread t owns float4 column t
// (columns 4t..4t+3) exclusively — no cross-thread reduction needed.
// Unroll 4 rows -> 4 independent LDG.128 per thread in flight.
// Epilogue is a single float4 store.
// ---------------------------------------------------------------------------
__global__ __launch_bounds__(64)
void segsum_kernel(const float* __restrict__ x,
                   const int*   __restrict__ node_num)
{
    const int b = blockIdx.x;
    const int t = threadIdx.x;                 // 0..63
    const int cnt   = __ldg(&node_num[b]);
    const int start = g_off[b];

    const float4* p = reinterpret_cast<const float4*>(x + (size_t)start * 256) + t;

    float4 a0 = make_float4(0.f, 0.f, 0.f, 0.f);
    float4 a1 = make_float4(0.f, 0.f, 0.f, 0.f);
    float4 a2 = make_float4(0.f, 0.f, 0.f, 0.f);
    float4 a3 = make_float4(0.f, 0.f, 0.f, 0.f);

    const int n4 = cnt >> 2;
    for (int i = 0; i < n4; ++i) {
        float4 r0 = p[0];
        float4 r1 = p[64];
        float4 r2 = p[128];
        float4 r3 = p[192];
        a0.x += r0.x; a0.y += r0.y; a0.z += r0.z; a0.w += r0.w;
        a1.x += r1.x; a1.y += r1.y; a1.z += r1.z; a1.w += r1.w;
        a2.x += r2.x; a2.y += r2.y; a2.z += r2.z; a2.w += r2.w;
        a3.x += r3.x; a3.y += r3.y; a3.z += r3.z; a3.w += r3.w;
        p += 256;
    }
    const int tail = cnt & 3;
    for (int r = 0; r < tail; ++r) {
        float4 r0 = p[0];
        a0.x += r0.x; a0.y += r0.y; a0.z += r0.z; a0.w += r0.w;
        p += 64;
    }

    float4 s;
    s.x = (a0.x + a1.x) + (a2.x + a3.x);
    s.y = (a0.y + a1.y) + (a2.y + a3.y);
    s.z = (a0.z + a1.z) + (a2.z + a3.z);
    s.w = (a0.w + a1.w) + (a2.w + a3.w);

    reinterpret_cast<float4*>(g_sum)[(size_t)b * 64 + t] = s;
}

// ---------------------------------------------------------------------------
// Kernel 3 (phase 2): one warp per segment. Reads the 1KB sum, computes
// sigmoid(sum/cnt . W[o] + b[o]) for o=0..3.
// Lane owns columns [4*lane..4*lane+3] and [128+4*lane..128+4*lane+3].
// After the shuffle tree, lane 0 holds ALL four complete sums and writes
// one float4 to out.
// ---------------------------------------------------------------------------
__global__ __launch_bounds__(256)
void gemm_kernel(const int*   __restrict__ node_num,
                 const float* __restrict__ W,     // [4,256]
                 const float* __restrict__ bias,  // [4]
                 float*       __restrict__ out,   // [B,4]
                 int B)
{
    const int warp = (blockIdx.x * blockDim.x + threadIdx.x) >> 5;
    const int lane = threadIdx.x & 31;
    if (warp >= B) return;

    const float4* s4 = reinterpret_cast<const float4*>(g_sum) + (size_t)warp * 64;
    const float4 s0 = s4[lane];
    const float4 s1 = s4[32 + lane];

    const int c0 = lane << 2;          // columns 4*lane
    const int c1 = 128 + (lane << 2);  // columns 128+4*lane

    float acc[4];
    #pragma unroll
    for (int o = 0; o < 4; ++o) {
        const float4 wa = *reinterpret_cast<const float4*>(W + o * 256 + c0);
        const float4 wb = *reinterpret_cast<const float4*>(W + o * 256 + c1);
        acc[o] = s0.x * wa.x + s0.y * wa.y + s0.z * wa.z + s0.w * wa.w
               + s1.x * wb.x + s1.y * wb.y + s1.z * wb.z + s1.w * wb.w;
    }

    #pragma unroll
    for (int off = 16; off > 0; off >>= 1) {
        acc[0] += __shfl_down_sync(0xFFFFFFFFu, acc[0], off);
        acc[1] += __shfl_down_sync(0xFFFFFFFFu, acc[1], off);
        acc[2] += __shfl_down_sync(0xFFFFFFFFu, acc[2], off);
        acc[3] += __shfl_down_sync(0xFFFFFFFFu, acc[3], off);
    }

    if (lane == 0) {
        const float inv = 1.0f / (float)__ldg(&node_num[warp]);
        float4 o4;
        o4.x = 1.0f / (1.0f + __expf(-(bias[0] + acc[0] * inv)));
        o4.y = 1.0f / (1.0f + __expf(-(bias[1] + acc[1] * inv)));
        o4.z = 1.0f / (1.0f + __expf(-(bias[2] + acc[2] * inv)));
        o4.w = 1.0f / (1.0f + __expf(-(bias[3] + acc[3] * inv)));
        reinterpret_cast<float4*>(out)[warp] = o4;
    }
}

extern "C" void kernel_launch(void* const* d_in, const int* in_sizes, int n_in,
                              void* d_out, int out_size) {
    const float* x        = (const float*)d_in[0];
    const int*   node_num = (const int*)  d_in[1];
    const float* W        = (const float*)d_in[2];
    const float* bias     = (const float*)d_in[3];
    float*       out      = (float*)d_out;

    const int B = in_sizes[1];   // 4096 segments

    scan_kernel<<<1, 1024>>>(node_num, B);
    segsum_kernel<<<B, 64>>>(x, node_num);
    gemm_kernel<<<(B + 7) / 8, 256>>>(node_num, W, bias, out, B);
}